// round 1
// baseline (speedup 1.0000x reference)
#include <cuda_runtime.h>
#include <cuda_bf16.h>
#include <math.h>

// Problem constants
#define DIMV   1024
#define NHEADS 16
#define BLKSZ  129
#define DKV    64
#define NBLK   32
#define BATCH  4
#define NLEN   (BLKSZ * NBLK)        // 4128
#define MROWS  (BATCH * NLEN)        // 16512

// Scratch (device globals; no allocation allowed)
__device__ float g_q[MROWS * DIMV];
__device__ float g_k[MROWS * DIMV];
__device__ float g_v[MROWS * DIMV];
__device__ float g_ao[MROWS * DIMV];

// ---------------------------------------------------------------------------
// SGEMM NT: C[M,N] = A[M,K] * B[N,K]^T (+ optional bias[N])
// M=16512, N=1024, K=1024 fixed. BM=BN=128, BK=16, 256 threads, 8x8/thread.
// ---------------------------------------------------------------------------
#define BM 128
#define BN 128
#define BK 16

__global__ __launch_bounds__(256, 2)
void gemm_nt(const float* __restrict__ A, const float* __restrict__ Bw,
             float* __restrict__ C, const float* __restrict__ bias)
{
    __shared__ float As[BK][BM];
    __shared__ float Bs[BK][BN];

    const int tid  = threadIdx.x;
    const int brow = blockIdx.y * BM;
    const int bcol = blockIdx.x * BN;

    // operand-fetch coords: split-half layout for conflict-free LDS.128
    const int tx4 = (tid & 15) * 4;   // 0..60
    const int ty4 = (tid >> 4) * 4;   // 0..60

    // loader coords: each thread loads 2 rows x 4 cols (float4) of each tile
    const int lrow = tid >> 2;        // 0..63
    const int lcol = (tid & 3) * 4;   // 0,4,8,12

    float acc[8][8];
    #pragma unroll
    for (int i = 0; i < 8; i++)
        #pragma unroll
        for (int j = 0; j < 8; j++) acc[i][j] = 0.f;

    for (int k0 = 0; k0 < 1024; k0 += BK) {
        #pragma unroll
        for (int half = 0; half < 2; half++) {
            int r = lrow + half * 64;
            float4 va = *(const float4*)&A [(size_t)(brow + r) * 1024 + k0 + lcol];
            As[lcol + 0][r] = va.x; As[lcol + 1][r] = va.y;
            As[lcol + 2][r] = va.z; As[lcol + 3][r] = va.w;
            float4 vb = *(const float4*)&Bw[(size_t)(bcol + r) * 1024 + k0 + lcol];
            Bs[lcol + 0][r] = vb.x; Bs[lcol + 1][r] = vb.y;
            Bs[lcol + 2][r] = vb.z; Bs[lcol + 3][r] = vb.w;
        }
        __syncthreads();

        #pragma unroll
        for (int kk = 0; kk < BK; kk++) {
            float ar[8], br[8];
            *(float4*)&ar[0] = *(const float4*)&As[kk][ty4];
            *(float4*)&ar[4] = *(const float4*)&As[kk][64 + ty4];
            *(float4*)&br[0] = *(const float4*)&Bs[kk][tx4];
            *(float4*)&br[4] = *(const float4*)&Bs[kk][64 + tx4];
            #pragma unroll
            for (int i = 0; i < 8; i++)
                #pragma unroll
                for (int j = 0; j < 8; j++)
                    acc[i][j] += ar[i] * br[j];
        }
        __syncthreads();
    }

    // epilogue: rows {ty4..ty4+3, 64+ty4..}, cols {tx4..tx4+3, 64+tx4..}
    #pragma unroll
    for (int i = 0; i < 8; i++) {
        int r = brow + ((i < 4) ? (ty4 + i) : (64 + ty4 + i - 4));
        #pragma unroll
        for (int jh = 0; jh < 2; jh++) {
            int c = bcol + jh * 64 + tx4;
            float4 v;
            v.x = acc[i][jh * 4 + 0];
            v.y = acc[i][jh * 4 + 1];
            v.z = acc[i][jh * 4 + 2];
            v.w = acc[i][jh * 4 + 3];
            if (bias) {
                v.x += bias[c + 0]; v.y += bias[c + 1];
                v.z += bias[c + 2]; v.w += bias[c + 3];
            }
            *(float4*)&C[(size_t)r * 1024 + c] = v;
        }
    }
}

// ---------------------------------------------------------------------------
// Per-block attention: one CTA per (b, blk, head). 129 queries x 129 keys,
// d=64. K/V staged in smem, score rows in smem (stride 129 -> conflict-free).
// Writes g_ao[b, n, h*64+d] (normalized).
// ---------------------------------------------------------------------------
__global__ void attn_block_kernel()
{
    const int h = blockIdx.x % NHEADS;
    const int j = (blockIdx.x / NHEADS) % NBLK;
    const int b = blockIdx.x / (NHEADS * NBLK);

    extern __shared__ float sm[];
    float* Ks = sm;                      // 129*64
    float* Vs = sm + BLKSZ * DKV;        // 129*64
    float* Ss = sm + 2 * BLKSZ * DKV;    // 129*129

    const size_t base = ((size_t)b * NLEN + (size_t)j * BLKSZ) * DIMV + h * DKV;

    // cooperative K/V load (float4)
    for (int idx = threadIdx.x; idx < BLKSZ * (DKV / 4); idx += blockDim.x) {
        int r  = idx / (DKV / 4);
        int c4 = (idx % (DKV / 4)) * 4;
        *(float4*)&Ks[r * DKV + c4] = *(const float4*)&g_k[base + (size_t)r * DIMV + c4];
        *(float4*)&Vs[r * DKV + c4] = *(const float4*)&g_v[base + (size_t)r * DIMV + c4];
    }
    __syncthreads();

    const int t = threadIdx.x;
    if (t < BLKSZ) {
        float qr[DKV];
        #pragma unroll
        for (int d = 0; d < DKV; d++) qr[d] = g_q[base + (size_t)t * DIMV + d];

        const float scale = 0.125f;   // 1/sqrt(64)
        float mx = -1e30f;
        float* srow = &Ss[t * BLKSZ];

        for (int kk = 0; kk < BLKSZ; kk++) {
            float s = 0.f;
            #pragma unroll
            for (int d = 0; d < DKV; d++) s += qr[d] * Ks[kk * DKV + d];
            s *= scale;
            srow[kk] = s;
            mx = fmaxf(mx, s);
        }

        float l = 0.f;
        for (int kk = 0; kk < BLKSZ; kk++) {
            float p = __expf(srow[kk] - mx);
            srow[kk] = p;
            l += p;
        }
        const float inv = 1.f / l;

        float acc[DKV];
        #pragma unroll
        for (int d = 0; d < DKV; d++) acc[d] = 0.f;
        for (int kk = 0; kk < BLKSZ; kk++) {
            float p = srow[kk];
            #pragma unroll
            for (int d = 0; d < DKV; d++) acc[d] += p * Vs[kk * DKV + d];
        }
        #pragma unroll
        for (int d = 0; d < DKV; d++)
            g_ao[base + (size_t)t * DIMV + d] = acc[d] * inv;
    }
}

// ---------------------------------------------------------------------------
// Global attention over the 32 block-leader tokens, added into token 0 of
// each block. One CTA per (b, h), 32 threads (thread = query block index).
// ---------------------------------------------------------------------------
__global__ void attn_global_kernel()
{
    const int h = blockIdx.x % NHEADS;
    const int b = blockIdx.x / NHEADS;
    const int t = threadIdx.x;           // query block index 0..31

    const size_t hb    = (size_t)h * DKV;
    const size_t qbase = ((size_t)b * NLEN + (size_t)t * BLKSZ) * DIMV + hb;

    float qr[DKV];
    #pragma unroll
    for (int d = 0; d < DKV; d++) qr[d] = g_q[qbase + d];

    const float scale = 0.125f;
    float sc[NBLK];
    float mx = -1e30f;
    for (int kk = 0; kk < NBLK; kk++) {
        const size_t kbase = ((size_t)b * NLEN + (size_t)kk * BLKSZ) * DIMV + hb;
        float s = 0.f;
        #pragma unroll
        for (int d = 0; d < DKV; d++) s += qr[d] * g_k[kbase + d];
        s *= scale;
        sc[kk] = s;
        mx = fmaxf(mx, s);
    }
    float l = 0.f;
    for (int kk = 0; kk < NBLK; kk++) {
        float p = __expf(sc[kk] - mx);
        sc[kk] = p;
        l += p;
    }
    const float inv = 1.f / l;

    float acc[DKV];
    #pragma unroll
    for (int d = 0; d < DKV; d++) acc[d] = 0.f;
    for (int kk = 0; kk < NBLK; kk++) {
        const size_t vbase = ((size_t)b * NLEN + (size_t)kk * BLKSZ) * DIMV + hb;
        float p = sc[kk];
        #pragma unroll
        for (int d = 0; d < DKV; d++) acc[d] += p * g_v[vbase + d];
    }
    #pragma unroll
    for (int d = 0; d < DKV; d++)
        g_ao[qbase + d] += acc[d] * inv;
}

// ---------------------------------------------------------------------------
// launcher
// ---------------------------------------------------------------------------
extern "C" void kernel_launch(void* const* d_in, const int* in_sizes, int n_in,
                              void* d_out, int out_size)
{
    const float* x  = (const float*)d_in[0];
    const float* Wq = (const float*)d_in[1];
    const float* Wk = (const float*)d_in[2];
    const float* Wv = (const float*)d_in[3];
    const float* Wo = (const float*)d_in[4];
    const float* bo = (const float*)d_in[5];
    float* out = (float*)d_out;

    float *qp, *kp, *vp, *aop;
    cudaGetSymbolAddress((void**)&qp,  g_q);
    cudaGetSymbolAddress((void**)&kp,  g_k);
    cudaGetSymbolAddress((void**)&vp,  g_v);
    cudaGetSymbolAddress((void**)&aop, g_ao);

    const int smem_attn = (2 * BLKSZ * DKV + BLKSZ * BLKSZ) * (int)sizeof(float);
    cudaFuncSetAttribute(attn_block_kernel,
                         cudaFuncAttributeMaxDynamicSharedMemorySize, smem_attn);

    dim3 ggrid(DIMV / BN, MROWS / BM);   // (8, 129)

    // QKV projections
    gemm_nt<<<ggrid, 256>>>(x, Wq, qp, nullptr);
    gemm_nt<<<ggrid, 256>>>(x, Wk, kp, nullptr);
    gemm_nt<<<ggrid, 256>>>(x, Wv, vp, nullptr);

    // per-block attention
    attn_block_kernel<<<BATCH * NBLK * NHEADS, 160, smem_attn>>>();

    // global (block-leader) attention added into token 0 of each block
    attn_global_kernel<<<BATCH * NHEADS, 32>>>();

    // output projection + bias
    gemm_nt<<<ggrid, 256>>>(aop, Wo, out, bo);
}

// round 3
// speedup vs baseline: 1.3266x; 1.3266x over previous
#include <cuda_runtime.h>
#include <cuda_bf16.h>
#include <math.h>
#include <stdint.h>

// Problem constants
#define DIMV   1024
#define NHEADS 16
#define BLKSZ  129
#define DKV    64
#define NBLK   32
#define BATCH  4
#define NLEN   (BLKSZ * NBLK)        // 4128
#define MROWS  (BATCH * NLEN)        // 16512

// Scratch (device globals; no allocation allowed)
__device__ float g_q[MROWS * DIMV];
__device__ float g_k[MROWS * DIMV];
__device__ float g_v[MROWS * DIMV];
__device__ float g_ao[MROWS * DIMV];
// bf16 hi/lo split buffers
__device__ __nv_bfloat16 g_xh[MROWS * DIMV];
__device__ __nv_bfloat16 g_xl[MROWS * DIMV];
__device__ __nv_bfloat16 g_aoh[MROWS * DIMV];
__device__ __nv_bfloat16 g_aol[MROWS * DIMV];
__device__ __nv_bfloat16 g_wh[4 * 1024 * 1024];   // Wq,Wk,Wv,Wo hi
__device__ __nv_bfloat16 g_wl[4 * 1024 * 1024];   // Wq,Wk,Wv,Wo lo

// ---------------------------------------------------------------------------
// helpers
// ---------------------------------------------------------------------------
__device__ __forceinline__ uint32_t smem_u32(const void* p) {
    uint32_t a;
    asm("{ .reg .u64 t; cvta.to.shared.u64 t, %1; cvt.u32.u64 %0, t; }"
        : "=r"(a) : "l"(p));
    return a;
}

__device__ __forceinline__ void cp16(uint32_t s, const void* g) {
    asm volatile("cp.async.cg.shared.global [%0], [%1], 16;" :: "r"(s), "l"(g));
}
#define CP_COMMIT() asm volatile("cp.async.commit_group;" ::: "memory")
#define CP_WAIT2()  asm volatile("cp.async.wait_group 2;" ::: "memory")

// SW64 swizzle (atom: 8 rows x 64B): XOR bits[4:5] with bits[7:8]
__device__ __forceinline__ uint32_t swz64(uint32_t off) {
    return off ^ ((off >> 3) & 0x30);
}

__device__ __forceinline__ void ldsm4(uint32_t* r, uint32_t addr) {
    asm volatile("ldmatrix.sync.aligned.m8n8.x4.shared.b16 {%0,%1,%2,%3}, [%4];"
                 : "=r"(r[0]), "=r"(r[1]), "=r"(r[2]), "=r"(r[3]) : "r"(addr));
}

__device__ __forceinline__ void mma16816(float* d, const uint32_t* a, const uint32_t* b) {
    asm volatile(
        "mma.sync.aligned.m16n8k16.row.col.f32.bf16.bf16.f32 "
        "{%0,%1,%2,%3}, {%4,%5,%6,%7}, {%8,%9}, {%0,%1,%2,%3};"
        : "+f"(d[0]), "+f"(d[1]), "+f"(d[2]), "+f"(d[3])
        : "r"(a[0]), "r"(a[1]), "r"(a[2]), "r"(a[3]), "r"(b[0]), "r"(b[1]));
}

// ---------------------------------------------------------------------------
// fp32 -> (hi, lo) bf16 split
// ---------------------------------------------------------------------------
__global__ void split_bf16_kernel(const float* __restrict__ src,
                                  __nv_bfloat16* __restrict__ hi,
                                  __nv_bfloat16* __restrict__ lo, int n4) {
    int i = blockIdx.x * blockDim.x + threadIdx.x;
    if (i >= n4) return;
    float4 v = ((const float4*)src)[i];
    __nv_bfloat16 h0 = __float2bfloat16(v.x);
    __nv_bfloat16 h1 = __float2bfloat16(v.y);
    __nv_bfloat16 h2 = __float2bfloat16(v.z);
    __nv_bfloat16 h3 = __float2bfloat16(v.w);
    __nv_bfloat16 l0 = __float2bfloat16(v.x - __bfloat162float(h0));
    __nv_bfloat16 l1 = __float2bfloat16(v.y - __bfloat162float(h1));
    __nv_bfloat16 l2 = __float2bfloat16(v.z - __bfloat162float(h2));
    __nv_bfloat16 l3 = __float2bfloat16(v.w - __bfloat162float(h3));
    ((__nv_bfloat162*)hi)[2 * i + 0] = __nv_bfloat162(h0, h1);
    ((__nv_bfloat162*)hi)[2 * i + 1] = __nv_bfloat162(h2, h3);
    ((__nv_bfloat162*)lo)[2 * i + 0] = __nv_bfloat162(l0, l1);
    ((__nv_bfloat162*)lo)[2 * i + 1] = __nv_bfloat162(l2, l3);
}

// ---------------------------------------------------------------------------
// HMMA bf16-split GEMM:  C[M,1024] = A[M,1024] * B[1024,1024]^T (+bias)
// A as (Ahi,Alo), B as (Bhi,Blo), fp32 accumulate: Ahi*Bhi + Ahi*Blo + Alo*Bhi.
// CTA tile 128x128, BK=32, 8 warps (4x2, each 32x64), 4-stage cp.async.
// ---------------------------------------------------------------------------
#define GM_BM 128
#define GM_BN 128
#define GM_BK 32
#define NSTAGE 4
#define STG_A_HI 0
#define STG_A_LO 8192
#define STG_B_HI 16384
#define STG_B_LO 24576
#define STG_BYTES 32768
#define GEMM_SMEM (NSTAGE * STG_BYTES)     // 131072
#define NCHUNK 32

__global__ __launch_bounds__(256, 1)
void gemm_tc(const __nv_bfloat16* __restrict__ Ahi, const __nv_bfloat16* __restrict__ Alo,
             const __nv_bfloat16* __restrict__ Bhi, const __nv_bfloat16* __restrict__ Blo,
             float* __restrict__ C, const float* __restrict__ bias)
{
    extern __shared__ char smem[];
    const uint32_t sb = smem_u32(smem);
    const int tid  = threadIdx.x;
    const int wid  = tid >> 5;
    const int lane = tid & 31;
    const int warp_m = wid >> 1;          // 0..3 -> 32 rows
    const int warp_n = wid & 1;           // 0..1 -> 64 cols
    const int brow = blockIdx.y * GM_BM;
    const int bcol = blockIdx.x * GM_BN;

    // loader indices: per stream 128 rows x 4 x 16B segs = 512 segs, 2/thread
    const int lr0 = tid >> 1;                    // rows 0..127
    const int ls0 = (tid & 1) * 2;               // segs {0,1} or {2,3} pairs

    auto load_stage = [&](int c) {
        const uint32_t st = sb + (c % NSTAGE) * STG_BYTES;
        const int k0 = c * GM_BK;
        #pragma unroll
        for (int i = 0; i < 2; i++) {
            int r = lr0, s = ls0 + i;
            uint32_t so = swz64((uint32_t)(r * 64 + s * 16));
            size_t ga = (size_t)(brow + r) * 1024 + k0 + s * 8;
            size_t gb = (size_t)(bcol + r) * 1024 + k0 + s * 8;
            cp16(st + STG_A_HI + so, Ahi + ga);
            cp16(st + STG_A_LO + so, Alo + ga);
            cp16(st + STG_B_HI + so, Bhi + gb);
            cp16(st + STG_B_LO + so, Blo + gb);
        }
        CP_COMMIT();
    };

    float acc[2][8][4];
    #pragma unroll
    for (int i = 0; i < 2; i++)
        #pragma unroll
        for (int j = 0; j < 8; j++)
            #pragma unroll
            for (int q = 0; q < 4; q++) acc[i][j][q] = 0.f;

    // prologue: stages 0..2
    load_stage(0); load_stage(1); load_stage(2);

    // ldmatrix lane addressing (within-stage byte offsets)
    // A: row = warp_m*32 + mf*16 + (lane&15); kb = ks*32 + (lane>>4)*16
    // B: row = warp_n*64 + g*16 + ((lane>>4)*8) + (lane&7); kb = ks*32 + ((lane>>3)&1)*16
    const int a_row_l = (lane & 15);
    const int a_kb_l  = (lane >> 4) * 16;
    const int b_row_l = ((lane >> 4) * 8) + (lane & 7);
    const int b_kb_l  = ((lane >> 3) & 1) * 16;

    #pragma unroll 1
    for (int c = 0; c < NCHUNK; c++) {
        CP_WAIT2();
        __syncthreads();

        if (c + 3 < NCHUNK) load_stage(c + 3);
        else { CP_COMMIT(); }

        const uint32_t st = sb + (c % NSTAGE) * STG_BYTES;

        #pragma unroll
        for (int ks = 0; ks < 2; ks++) {
            uint32_t ah[2][4], al[2][4];
            #pragma unroll
            for (int mf = 0; mf < 2; mf++) {
                int row = warp_m * 32 + mf * 16 + a_row_l;
                uint32_t off = swz64((uint32_t)(row * 64 + ks * 32 + a_kb_l));
                ldsm4(ah[mf], st + STG_A_HI + off);
                ldsm4(al[mf], st + STG_A_LO + off);
            }
            uint32_t bh[4][4], bl[4][4];
            #pragma unroll
            for (int g = 0; g < 4; g++) {
                int row = warp_n * 64 + g * 16 + b_row_l;
                uint32_t off = swz64((uint32_t)(row * 64 + ks * 32 + b_kb_l));
                ldsm4(bh[g], st + STG_B_HI + off);
                ldsm4(bl[g], st + STG_B_LO + off);
            }
            #pragma unroll
            for (int mf = 0; mf < 2; mf++)
                #pragma unroll
                for (int g = 0; g < 4; g++)
                    #pragma unroll
                    for (int h = 0; h < 2; h++) {
                        float* d = acc[mf][g * 2 + h];
                        mma16816(d, ah[mf], &bh[g][h * 2]);   // hi*hi
                        mma16816(d, ah[mf], &bl[g][h * 2]);   // hi*lo
                        mma16816(d, al[mf], &bh[g][h * 2]);   // lo*hi
                    }
        }
        __syncthreads();
    }

    // epilogue: direct register -> gmem
    #pragma unroll
    for (int mf = 0; mf < 2; mf++) {
        int r0 = brow + warp_m * 32 + mf * 16 + (lane >> 2);
        #pragma unroll
        for (int nf = 0; nf < 8; nf++) {
            int col = bcol + warp_n * 64 + nf * 8 + (lane & 3) * 2;
            float b0 = 0.f, b1 = 0.f;
            if (bias) { b0 = bias[col]; b1 = bias[col + 1]; }
            float2 v0 = make_float2(acc[mf][nf][0] + b0, acc[mf][nf][1] + b1);
            float2 v1 = make_float2(acc[mf][nf][2] + b0, acc[mf][nf][3] + b1);
            *(float2*)&C[(size_t)r0 * 1024 + col]       = v0;
            *(float2*)&C[(size_t)(r0 + 8) * 1024 + col] = v1;
        }
    }
}

// ---------------------------------------------------------------------------
// Per-block attention: one CTA per (b, blk, head). 129 q x 129 k, d=64.
// K + scores in smem (99.6KB -> 2 CTAs/SM). V read from gmem (broadcast).
// ---------------------------------------------------------------------------
__global__ void attn_block_kernel()
{
    const int h = blockIdx.x % NHEADS;
    const int j = (blockIdx.x / NHEADS) % NBLK;
    const int b = blockIdx.x / (NHEADS * NBLK);

    extern __shared__ float sm[];
    float* Ks = sm;                      // 129*64
    float* Ss = sm + BLKSZ * DKV;        // 129*129

    const size_t base = ((size_t)b * NLEN + (size_t)j * BLKSZ) * DIMV + h * DKV;

    for (int idx = threadIdx.x; idx < BLKSZ * (DKV / 4); idx += blockDim.x) {
        int r  = idx / (DKV / 4);
        int c4 = (idx % (DKV / 4)) * 4;
        *(float4*)&Ks[r * DKV + c4] = *(const float4*)&g_k[base + (size_t)r * DIMV + c4];
    }
    __syncthreads();

    const int t = threadIdx.x;
    if (t < BLKSZ) {
        float qr[DKV];
        #pragma unroll
        for (int d = 0; d < DKV; d++) qr[d] = g_q[base + (size_t)t * DIMV + d];

        const float scale = 0.125f;
        float mx = -1e30f;
        float* srow = &Ss[t * BLKSZ];

        for (int kk = 0; kk < BLKSZ; kk++) {
            float s = 0.f;
            #pragma unroll
            for (int d = 0; d < DKV; d++) s += qr[d] * Ks[kk * DKV + d];
            s *= scale;
            srow[kk] = s;
            mx = fmaxf(mx, s);
        }

        float l = 0.f;
        for (int kk = 0; kk < BLKSZ; kk++) {
            float p = __expf(srow[kk] - mx);
            srow[kk] = p;
            l += p;
        }
        const float inv = 1.f / l;

        float acc[DKV];
        #pragma unroll
        for (int d = 0; d < DKV; d++) acc[d] = 0.f;
        const float4* vb = (const float4*)&g_v[base];
        for (int kk = 0; kk < BLKSZ; kk++) {
            float p = srow[kk];
            const float4* vr = vb + (size_t)kk * (DIMV / 4);
            #pragma unroll
            for (int d4 = 0; d4 < DKV / 4; d4++) {
                float4 v = __ldg(&vr[d4]);
                acc[d4 * 4 + 0] += p * v.x;
                acc[d4 * 4 + 1] += p * v.y;
                acc[d4 * 4 + 2] += p * v.z;
                acc[d4 * 4 + 3] += p * v.w;
            }
        }
        #pragma unroll
        for (int d = 0; d < DKV; d++)
            g_ao[base + (size_t)t * DIMV + d] = acc[d] * inv;
    }
}

// ---------------------------------------------------------------------------
// Global attention over the 32 block-leader tokens (added into token 0).
// ---------------------------------------------------------------------------
__global__ void attn_global_kernel()
{
    const int h = blockIdx.x % NHEADS;
    const int b = blockIdx.x / NHEADS;
    const int t = threadIdx.x;           // query block index 0..31

    const size_t hb    = (size_t)h * DKV;
    const size_t qbase = ((size_t)b * NLEN + (size_t)t * BLKSZ) * DIMV + hb;

    float qr[DKV];
    #pragma unroll
    for (int d = 0; d < DKV; d++) qr[d] = g_q[qbase + d];

    const float scale = 0.125f;
    float sc[NBLK];
    float mx = -1e30f;
    for (int kk = 0; kk < NBLK; kk++) {
        const size_t kbase = ((size_t)b * NLEN + (size_t)kk * BLKSZ) * DIMV + hb;
        float s = 0.f;
        #pragma unroll
        for (int d = 0; d < DKV; d++) s += qr[d] * g_k[kbase + d];
        s *= scale;
        sc[kk] = s;
        mx = fmaxf(mx, s);
    }
    float l = 0.f;
    for (int kk = 0; kk < NBLK; kk++) {
        float p = __expf(sc[kk] - mx);
        sc[kk] = p;
        l += p;
    }
    const float inv = 1.f / l;

    float acc[DKV];
    #pragma unroll
    for (int d = 0; d < DKV; d++) acc[d] = 0.f;
    for (int kk = 0; kk < NBLK; kk++) {
        const size_t vbase = ((size_t)b * NLEN + (size_t)kk * BLKSZ) * DIMV + hb;
        float p = sc[kk];
        #pragma unroll
        for (int d = 0; d < DKV; d++) acc[d] += p * g_v[vbase + d];
    }
    #pragma unroll
    for (int d = 0; d < DKV; d++)
        g_ao[qbase + d] += acc[d] * inv;
}

// ---------------------------------------------------------------------------
// launcher
// ---------------------------------------------------------------------------
extern "C" void kernel_launch(void* const* d_in, const int* in_sizes, int n_in,
                              void* d_out, int out_size)
{
    const float* x  = (const float*)d_in[0];
    const float* Wq = (const float*)d_in[1];
    const float* Wk = (const float*)d_in[2];
    const float* Wv = (const float*)d_in[3];
    const float* Wo = (const float*)d_in[4];
    const float* bo = (const float*)d_in[5];
    float* out = (float*)d_out;

    float *qp, *kp, *vp, *aop;
    cudaGetSymbolAddress((void**)&qp,  g_q);
    cudaGetSymbolAddress((void**)&kp,  g_k);
    cudaGetSymbolAddress((void**)&vp,  g_v);
    cudaGetSymbolAddress((void**)&aop, g_ao);
    __nv_bfloat16 *xh, *xl, *aoh, *aol, *wh, *wl;
    cudaGetSymbolAddress((void**)&xh,  g_xh);
    cudaGetSymbolAddress((void**)&xl,  g_xl);
    cudaGetSymbolAddress((void**)&aoh, g_aoh);
    cudaGetSymbolAddress((void**)&aol, g_aol);
    cudaGetSymbolAddress((void**)&wh,  g_wh);
    cudaGetSymbolAddress((void**)&wl,  g_wl);

    const int smem_attn = (BLKSZ * DKV + BLKSZ * BLKSZ) * (int)sizeof(float);
    cudaFuncSetAttribute(gemm_tc,
                         cudaFuncAttributeMaxDynamicSharedMemorySize, GEMM_SMEM);
    cudaFuncSetAttribute(attn_block_kernel,
                         cudaFuncAttributeMaxDynamicSharedMemorySize, smem_attn);

    const int WSZ = 1024 * 1024;

    // splits
    {
        int n4 = MROWS * DIMV / 4;
        split_bf16_kernel<<<(n4 + 255) / 256, 256>>>(x, xh, xl, n4);
        int w4 = WSZ / 4;
        split_bf16_kernel<<<(w4 + 255) / 256, 256>>>(Wq, wh + 0 * WSZ, wl + 0 * WSZ, w4);
        split_bf16_kernel<<<(w4 + 255) / 256, 256>>>(Wk, wh + 1 * WSZ, wl + 1 * WSZ, w4);
        split_bf16_kernel<<<(w4 + 255) / 256, 256>>>(Wv, wh + 2 * WSZ, wl + 2 * WSZ, w4);
        split_bf16_kernel<<<(w4 + 255) / 256, 256>>>(Wo, wh + 3 * WSZ, wl + 3 * WSZ, w4);
    }

    dim3 ggrid(DIMV / GM_BN, MROWS / GM_BM);   // (8, 129)

    // QKV projections (HMMA)
    gemm_tc<<<ggrid, 256, GEMM_SMEM>>>(xh, xl, wh + 0 * WSZ, wl + 0 * WSZ, qp, nullptr);
    gemm_tc<<<ggrid, 256, GEMM_SMEM>>>(xh, xl, wh + 1 * WSZ, wl + 1 * WSZ, kp, nullptr);
    gemm_tc<<<ggrid, 256, GEMM_SMEM>>>(xh, xl, wh + 2 * WSZ, wl + 2 * WSZ, vp, nullptr);

    // attention
    attn_block_kernel<<<BATCH * NBLK * NHEADS, 160, smem_attn>>>();
    attn_global_kernel<<<BATCH * NHEADS, 32>>>();

    // output projection + bias
    {
        int n4 = MROWS * DIMV / 4;
        split_bf16_kernel<<<(n4 + 255) / 256, 256>>>(aop, aoh, aol, n4);
    }
    gemm_tc<<<ggrid, 256, GEMM_SMEM>>>(aoh, aol, wh + 3 * WSZ, wl + 3 * WSZ, out, bo);
}

// round 4
// speedup vs baseline: 1.4625x; 1.1024x over previous
#include <cuda_runtime.h>
#include <cuda_bf16.h>
#include <math.h>
#include <stdint.h>

// Problem constants
#define DIMV   1024
#define NHEADS 16
#define BLKSZ  129
#define DKV    64
#define NBLK   32
#define BATCH  4
#define NLEN   (BLKSZ * NBLK)        // 4128
#define MROWS  (BATCH * NLEN)        // 16512
#define WSZ    (1024 * 1024)

// Scratch (device globals; no allocation allowed)
__device__ float g_q[MROWS * DIMV];
__device__ float g_k[MROWS * DIMV];
__device__ float g_v[MROWS * DIMV];
// bf16 hi/lo split buffers
__device__ __nv_bfloat16 g_xh[MROWS * DIMV];
__device__ __nv_bfloat16 g_xl[MROWS * DIMV];
__device__ __nv_bfloat16 g_aoh[MROWS * DIMV];
__device__ __nv_bfloat16 g_aol[MROWS * DIMV];
__device__ __nv_bfloat16 g_wh[4 * WSZ];   // Wq,Wk,Wv,Wo hi
__device__ __nv_bfloat16 g_wl[4 * WSZ];   // Wq,Wk,Wv,Wo lo

// ---------------------------------------------------------------------------
// helpers
// ---------------------------------------------------------------------------
__device__ __forceinline__ uint32_t smem_u32(const void* p) {
    uint32_t a;
    asm("{ .reg .u64 t; cvta.to.shared.u64 t, %1; cvt.u32.u64 %0, t; }"
        : "=r"(a) : "l"(p));
    return a;
}

__device__ __forceinline__ void cp16(uint32_t s, const void* g) {
    asm volatile("cp.async.cg.shared.global [%0], [%1], 16;" :: "r"(s), "l"(g));
}
#define CP_COMMIT() asm volatile("cp.async.commit_group;" ::: "memory")
#define CP_WAIT1()  asm volatile("cp.async.wait_group 1;" ::: "memory")

// SW64 swizzle (atom: 8 rows x 64B)
__device__ __forceinline__ uint32_t swz64(uint32_t off) {
    return off ^ ((off >> 3) & 0x30);
}

__device__ __forceinline__ void ldsm4(uint32_t* r, uint32_t addr) {
    asm volatile("ldmatrix.sync.aligned.m8n8.x4.shared.b16 {%0,%1,%2,%3}, [%4];"
                 : "=r"(r[0]), "=r"(r[1]), "=r"(r[2]), "=r"(r[3]) : "r"(addr));
}

__device__ __forceinline__ void mma16816(float* d, const uint32_t* a, const uint32_t* b) {
    asm volatile(
        "mma.sync.aligned.m16n8k16.row.col.f32.bf16.bf16.f32 "
        "{%0,%1,%2,%3}, {%4,%5,%6,%7}, {%8,%9}, {%0,%1,%2,%3};"
        : "+f"(d[0]), "+f"(d[1]), "+f"(d[2]), "+f"(d[3])
        : "r"(a[0]), "r"(a[1]), "r"(a[2]), "r"(a[3]), "r"(b[0]), "r"(b[1]));
}

// ---------------------------------------------------------------------------
// fp32 -> (hi, lo) bf16 splits
// ---------------------------------------------------------------------------
__device__ __forceinline__ void split1(float v, __nv_bfloat16& h, __nv_bfloat16& l) {
    h = __float2bfloat16(v);
    l = __float2bfloat16(v - __bfloat162float(h));
}

__global__ void split_bf16_kernel(const float* __restrict__ src,
                                  __nv_bfloat16* __restrict__ hi,
                                  __nv_bfloat16* __restrict__ lo, int n4) {
    int i = blockIdx.x * blockDim.x + threadIdx.x;
    if (i >= n4) return;
    float4 v = ((const float4*)src)[i];
    __nv_bfloat16 h0, h1, h2, h3, l0, l1, l2, l3;
    split1(v.x, h0, l0); split1(v.y, h1, l1);
    split1(v.z, h2, l2); split1(v.w, h3, l3);
    ((__nv_bfloat162*)hi)[2 * i + 0] = __nv_bfloat162(h0, h1);
    ((__nv_bfloat162*)hi)[2 * i + 1] = __nv_bfloat162(h2, h3);
    ((__nv_bfloat162*)lo)[2 * i + 0] = __nv_bfloat162(l0, l1);
    ((__nv_bfloat162*)lo)[2 * i + 1] = __nv_bfloat162(l2, l3);
}

// all 4 weights in one launch; 1024 blocks per weight
__global__ void split_w4_kernel(const float* __restrict__ s0, const float* __restrict__ s1,
                                const float* __restrict__ s2, const float* __restrict__ s3,
                                __nv_bfloat16* __restrict__ hi, __nv_bfloat16* __restrict__ lo) {
    int w = blockIdx.x >> 10;
    int i = (blockIdx.x & 1023) * 256 + threadIdx.x;     // < 262144
    const float* src = (w == 0) ? s0 : (w == 1) ? s1 : (w == 2) ? s2 : s3;
    float4 v = ((const float4*)src)[i];
    __nv_bfloat16 h0, h1, h2, h3, l0, l1, l2, l3;
    split1(v.x, h0, l0); split1(v.y, h1, l1);
    split1(v.z, h2, l2); split1(v.w, h3, l3);
    __nv_bfloat16* hp = hi + (size_t)w * WSZ;
    __nv_bfloat16* lp = lo + (size_t)w * WSZ;
    ((__nv_bfloat162*)hp)[2 * i + 0] = __nv_bfloat162(h0, h1);
    ((__nv_bfloat162*)hp)[2 * i + 1] = __nv_bfloat162(h2, h3);
    ((__nv_bfloat162*)lp)[2 * i + 0] = __nv_bfloat162(l0, l1);
    ((__nv_bfloat162*)lp)[2 * i + 1] = __nv_bfloat162(l2, l3);
}

// ---------------------------------------------------------------------------
// HMMA bf16-split GEMM, optionally fused over several weight matrices.
// C_sel[M,1024] = A[M,1024] * B_sel[1024,1024]^T (+bias)
// sel = blockIdx.x / 8 (8 col-blocks of 128 per matrix).
// CTA tile 128x128, BK=32, 8 warps (4x2, each 32x64), 3-stage cp.async,
// 2 CTAs/SM.
// ---------------------------------------------------------------------------
#define GM_BK 32
#define NSTAGE 3
#define STG_A_HI 0
#define STG_A_LO 8192
#define STG_B_HI 16384
#define STG_B_LO 24576
#define STG_BYTES 32768
#define GEMM_SMEM (NSTAGE * STG_BYTES)     // 98304
#define NCHUNK 32

__global__ __launch_bounds__(256, 2)
void gemm_tc(const __nv_bfloat16* __restrict__ Ahi, const __nv_bfloat16* __restrict__ Alo,
             const __nv_bfloat16* __restrict__ Bhi, const __nv_bfloat16* __restrict__ Blo,
             float* o0, float* o1, float* o2,
             const float* __restrict__ bias)
{
    extern __shared__ char smem[];
    const uint32_t sb = smem_u32(smem);
    const int tid  = threadIdx.x;
    const int wid  = tid >> 5;
    const int lane = tid & 31;
    const int warp_m = wid >> 1;
    const int warp_n = wid & 1;
    const int sel  = blockIdx.x >> 3;
    const int brow = blockIdx.y * 128;
    const int bcol = (blockIdx.x & 7) * 128;

    const __nv_bfloat16* Bh = Bhi + (size_t)sel * WSZ;
    const __nv_bfloat16* Bl = Blo + (size_t)sel * WSZ;
    float* C = (sel == 0) ? o0 : (sel == 1) ? o1 : o2;

    const int lr0 = tid >> 1;
    const int ls0 = (tid & 1) * 2;

    auto load_stage = [&](int c) {
        const uint32_t st = sb + (c % NSTAGE) * STG_BYTES;
        const int k0 = c * GM_BK;
        #pragma unroll
        for (int i = 0; i < 2; i++) {
            int s = ls0 + i;
            uint32_t so = swz64((uint32_t)(lr0 * 64 + s * 16));
            size_t ga = (size_t)(brow + lr0) * 1024 + k0 + s * 8;
            size_t gb = (size_t)(bcol + lr0) * 1024 + k0 + s * 8;
            cp16(st + STG_A_HI + so, Ahi + ga);
            cp16(st + STG_A_LO + so, Alo + ga);
            cp16(st + STG_B_HI + so, Bh + gb);
            cp16(st + STG_B_LO + so, Bl + gb);
        }
        CP_COMMIT();
    };

    float acc[2][8][4];
    #pragma unroll
    for (int i = 0; i < 2; i++)
        #pragma unroll
        for (int j = 0; j < 8; j++)
            #pragma unroll
            for (int q = 0; q < 4; q++) acc[i][j][q] = 0.f;

    load_stage(0);
    load_stage(1);

    const int a_row_l = (lane & 15);
    const int a_kb_l  = (lane >> 4) * 16;
    const int b_row_l = ((lane >> 4) * 8) + (lane & 7);
    const int b_kb_l  = ((lane >> 3) & 1) * 16;

    #pragma unroll 1
    for (int c = 0; c < NCHUNK; c++) {
        CP_WAIT1();
        __syncthreads();
        if (c + 2 < NCHUNK) load_stage(c + 2);
        else CP_COMMIT();

        const uint32_t st = sb + (c % NSTAGE) * STG_BYTES;

        #pragma unroll
        for (int ks = 0; ks < 2; ks++) {
            uint32_t ah[2][4], al[2][4];
            #pragma unroll
            for (int mf = 0; mf < 2; mf++) {
                int row = warp_m * 32 + mf * 16 + a_row_l;
                uint32_t off = swz64((uint32_t)(row * 64 + ks * 32 + a_kb_l));
                ldsm4(ah[mf], st + STG_A_HI + off);
                ldsm4(al[mf], st + STG_A_LO + off);
            }
            #pragma unroll
            for (int g = 0; g < 4; g++) {
                int row = warp_n * 64 + g * 16 + b_row_l;
                uint32_t off = swz64((uint32_t)(row * 64 + ks * 32 + b_kb_l));
                uint32_t bh[4], bl[4];
                ldsm4(bh, st + STG_B_HI + off);
                ldsm4(bl, st + STG_B_LO + off);
                #pragma unroll
                for (int mf = 0; mf < 2; mf++)
                    #pragma unroll
                    for (int h = 0; h < 2; h++) {
                        float* d = acc[mf][g * 2 + h];
                        mma16816(d, ah[mf], &bh[h * 2]);   // hi*hi
                        mma16816(d, ah[mf], &bl[h * 2]);   // hi*lo
                        mma16816(d, al[mf], &bh[h * 2]);   // lo*hi
                    }
            }
        }
    }

    // epilogue
    #pragma unroll
    for (int mf = 0; mf < 2; mf++) {
        int r0 = brow + warp_m * 32 + mf * 16 + (lane >> 2);
        #pragma unroll
        for (int nf = 0; nf < 8; nf++) {
            int col = bcol + warp_n * 64 + nf * 8 + (lane & 3) * 2;
            float b0 = 0.f, b1 = 0.f;
            if (bias) { b0 = bias[col]; b1 = bias[col + 1]; }
            float2 v0 = make_float2(acc[mf][nf][0] + b0, acc[mf][nf][1] + b1);
            float2 v1 = make_float2(acc[mf][nf][2] + b0, acc[mf][nf][3] + b1);
            *(float2*)&C[(size_t)r0 * 1024 + col]       = v0;
            *(float2*)&C[(size_t)(r0 + 8) * 1024 + col] = v1;
        }
    }
}

// ---------------------------------------------------------------------------
// Per-block attention: one CTA per (b, blk, head). 129 q x 129 k, d=64.
// K + scores in smem; V from gmem (broadcast). Writes hi/lo bf16 split
// directly (fused with downstream O-GEMM input prep).
// ---------------------------------------------------------------------------
__global__ void attn_block_kernel()
{
    const int h = blockIdx.x % NHEADS;
    const int j = (blockIdx.x / NHEADS) % NBLK;
    const int b = blockIdx.x / (NHEADS * NBLK);

    extern __shared__ float sm[];
    float* Ks = sm;                      // 129*64
    float* Ss = sm + BLKSZ * DKV;        // 129*129

    const size_t base = ((size_t)b * NLEN + (size_t)j * BLKSZ) * DIMV + h * DKV;

    for (int idx = threadIdx.x; idx < BLKSZ * (DKV / 4); idx += blockDim.x) {
        int r  = idx / (DKV / 4);
        int c4 = (idx % (DKV / 4)) * 4;
        *(float4*)&Ks[r * DKV + c4] = *(const float4*)&g_k[base + (size_t)r * DIMV + c4];
    }
    __syncthreads();

    const int t = threadIdx.x;
    if (t < BLKSZ) {
        float qr[DKV];
        #pragma unroll
        for (int d = 0; d < DKV; d++) qr[d] = g_q[base + (size_t)t * DIMV + d];

        const float scale = 0.125f;
        float mx = -1e30f;
        float* srow = &Ss[t * BLKSZ];

        for (int kk = 0; kk < BLKSZ; kk++) {
            float s = 0.f;
            #pragma unroll
            for (int d = 0; d < DKV; d++) s += qr[d] * Ks[kk * DKV + d];
            s *= scale;
            srow[kk] = s;
            mx = fmaxf(mx, s);
        }

        float l = 0.f;
        for (int kk = 0; kk < BLKSZ; kk++) {
            float p = __expf(srow[kk] - mx);
            srow[kk] = p;
            l += p;
        }
        const float inv = 1.f / l;

        float acc[DKV];
        #pragma unroll
        for (int d = 0; d < DKV; d++) acc[d] = 0.f;
        const float4* vb = (const float4*)&g_v[base];
        for (int kk = 0; kk < BLKSZ; kk++) {
            float p = srow[kk];
            const float4* vr = vb + (size_t)kk * (DIMV / 4);
            #pragma unroll
            for (int d4 = 0; d4 < DKV / 4; d4++) {
                float4 v = __ldg(&vr[d4]);
                acc[d4 * 4 + 0] += p * v.x;
                acc[d4 * 4 + 1] += p * v.y;
                acc[d4 * 4 + 2] += p * v.z;
                acc[d4 * 4 + 3] += p * v.w;
            }
        }
        const size_t ob = base + (size_t)t * DIMV;
        #pragma unroll
        for (int d2 = 0; d2 < DKV / 2; d2++) {
            float v0 = acc[2 * d2] * inv, v1 = acc[2 * d2 + 1] * inv;
            __nv_bfloat16 h0, h1, l0, l1;
            split1(v0, h0, l0); split1(v1, h1, l1);
            *(__nv_bfloat162*)&g_aoh[ob + 2 * d2] = __nv_bfloat162(h0, h1);
            *(__nv_bfloat162*)&g_aol[ob + 2 * d2] = __nv_bfloat162(l0, l1);
        }
    }
}

// ---------------------------------------------------------------------------
// Global attention over the 32 block-leader tokens (added into token 0).
// Reads/updates the hi/lo split representation.
// ---------------------------------------------------------------------------
__global__ void attn_global_kernel()
{
    const int h = blockIdx.x % NHEADS;
    const int b = blockIdx.x / NHEADS;
    const int t = threadIdx.x;           // query block index 0..31

    const size_t hb    = (size_t)h * DKV;
    const size_t qbase = ((size_t)b * NLEN + (size_t)t * BLKSZ) * DIMV + hb;

    float qr[DKV];
    #pragma unroll
    for (int d = 0; d < DKV; d++) qr[d] = g_q[qbase + d];

    const float scale = 0.125f;
    float sc[NBLK];
    float mx = -1e30f;
    for (int kk = 0; kk < NBLK; kk++) {
        const size_t kbase = ((size_t)b * NLEN + (size_t)kk * BLKSZ) * DIMV + hb;
        float s = 0.f;
        #pragma unroll
        for (int d = 0; d < DKV; d++) s += qr[d] * g_k[kbase + d];
        s *= scale;
        sc[kk] = s;
        mx = fmaxf(mx, s);
    }
    float l = 0.f;
    for (int kk = 0; kk < NBLK; kk++) {
        float p = __expf(sc[kk] - mx);
        sc[kk] = p;
        l += p;
    }
    const float inv = 1.f / l;

    float acc[DKV];
    #pragma unroll
    for (int d = 0; d < DKV; d++) acc[d] = 0.f;
    for (int kk = 0; kk < NBLK; kk++) {
        const size_t vbase = ((size_t)b * NLEN + (size_t)kk * BLKSZ) * DIMV + hb;
        float p = sc[kk];
        #pragma unroll
        for (int d = 0; d < DKV; d++) acc[d] += p * g_v[vbase + d];
    }
    #pragma unroll
    for (int d = 0; d < DKV; d++) {
        float cur = __bfloat162float(g_aoh[qbase + d]) + __bfloat162float(g_aol[qbase + d]);
        float nv  = cur + acc[d] * inv;
        __nv_bfloat16 hh, ll;
        split1(nv, hh, ll);
        g_aoh[qbase + d] = hh;
        g_aol[qbase + d] = ll;
    }
}

// ---------------------------------------------------------------------------
// launcher
// ---------------------------------------------------------------------------
extern "C" void kernel_launch(void* const* d_in, const int* in_sizes, int n_in,
                              void* d_out, int out_size)
{
    const float* x  = (const float*)d_in[0];
    const float* Wq = (const float*)d_in[1];
    const float* Wk = (const float*)d_in[2];
    const float* Wv = (const float*)d_in[3];
    const float* Wo = (const float*)d_in[4];
    const float* bo = (const float*)d_in[5];
    float* out = (float*)d_out;

    float *qp, *kp, *vp;
    cudaGetSymbolAddress((void**)&qp,  g_q);
    cudaGetSymbolAddress((void**)&kp,  g_k);
    cudaGetSymbolAddress((void**)&vp,  g_v);
    __nv_bfloat16 *xh, *xl, *aoh, *aol, *wh, *wl;
    cudaGetSymbolAddress((void**)&xh,  g_xh);
    cudaGetSymbolAddress((void**)&xl,  g_xl);
    cudaGetSymbolAddress((void**)&aoh, g_aoh);
    cudaGetSymbolAddress((void**)&aol, g_aol);
    cudaGetSymbolAddress((void**)&wh,  g_wh);
    cudaGetSymbolAddress((void**)&wl,  g_wl);

    const int smem_attn = (BLKSZ * DKV + BLKSZ * BLKSZ) * (int)sizeof(float);
    cudaFuncSetAttribute(gemm_tc,
                         cudaFuncAttributeMaxDynamicSharedMemorySize, GEMM_SMEM);
    cudaFuncSetAttribute(attn_block_kernel,
                         cudaFuncAttributeMaxDynamicSharedMemorySize, smem_attn);

    // launch 0: all weight splits
    split_w4_kernel<<<4096, 256>>>(Wq, Wk, Wv, Wo, wh, wl);
    // launch 1: x split
    {
        int n4 = MROWS * DIMV / 4;
        split_bf16_kernel<<<(n4 + 255) / 256, 256>>>(x, xh, xl, n4);
    }
    // launch 2: fused QKV projection
    gemm_tc<<<dim3(24, MROWS / 128), 256, GEMM_SMEM>>>(
        xh, xl, wh, wl, qp, kp, vp, nullptr);
    // launch 3: per-block attention (writes hi/lo split directly)
    attn_block_kernel<<<BATCH * NBLK * NHEADS, 160, smem_attn>>>();
    // launch 4: global leader-token attention (updates split)
    attn_global_kernel<<<BATCH * NHEADS, 32>>>();
    // launch 5: output projection + bias  (ncu capture slot)
    gemm_tc<<<dim3(8, MROWS / 128), 256, GEMM_SMEM>>>(
        aoh, aol, wh + 3 * (size_t)WSZ, wl + 3 * (size_t)WSZ, out, out, out, bo);
}

// round 6
// speedup vs baseline: 2.1764x; 1.4881x over previous
#include <cuda_runtime.h>
#include <cuda_bf16.h>
#include <math.h>
#include <stdint.h>

// Problem constants
#define DIMV   1024
#define NHEADS 16
#define BLKSZ  129
#define DKV    64
#define NBLK   32
#define BATCH  4
#define NLEN   (BLKSZ * NBLK)        // 4128
#define MROWS  (BATCH * NLEN)        // 16512
#define WSZ    (1024 * 1024)

// Scratch (device globals; no allocation allowed)
__device__ float g_q[MROWS * DIMV];
__device__ float g_k[MROWS * DIMV];
__device__ float g_v[MROWS * DIMV];
// bf16 hi/lo split buffers
__device__ __nv_bfloat16 g_xh[MROWS * DIMV];
__device__ __nv_bfloat16 g_xl[MROWS * DIMV];
__device__ __nv_bfloat16 g_aoh[MROWS * DIMV];
__device__ __nv_bfloat16 g_aol[MROWS * DIMV];
__device__ __nv_bfloat16 g_wh[4 * WSZ];   // Wq,Wk,Wv,Wo hi
__device__ __nv_bfloat16 g_wl[4 * WSZ];   // Wq,Wk,Wv,Wo lo

// ---------------------------------------------------------------------------
// helpers
// ---------------------------------------------------------------------------
__device__ __forceinline__ uint32_t smem_u32(const void* p) {
    uint32_t a;
    asm("{ .reg .u64 t; cvta.to.shared.u64 t, %1; cvt.u32.u64 %0, t; }"
        : "=r"(a) : "l"(p));
    return a;
}

__device__ __forceinline__ void cp16(uint32_t s, const void* g) {
    asm volatile("cp.async.cg.shared.global [%0], [%1], 16;" :: "r"(s), "l"(g));
}
#define CP_COMMIT() asm volatile("cp.async.commit_group;" ::: "memory")
#define CP_WAIT1()  asm volatile("cp.async.wait_group 1;" ::: "memory")

// SW64 swizzle (atom: 8 rows x 64B)
__device__ __forceinline__ uint32_t swz64(uint32_t off) {
    return off ^ ((off >> 3) & 0x30);
}

__device__ __forceinline__ void ldsm4(uint32_t* r, uint32_t addr) {
    asm volatile("ldmatrix.sync.aligned.m8n8.x4.shared.b16 {%0,%1,%2,%3}, [%4];"
                 : "=r"(r[0]), "=r"(r[1]), "=r"(r[2]), "=r"(r[3]) : "r"(addr));
}

__device__ __forceinline__ void mma16816(float* d, const uint32_t* a, const uint32_t* b) {
    asm volatile(
        "mma.sync.aligned.m16n8k16.row.col.f32.bf16.bf16.f32 "
        "{%0,%1,%2,%3}, {%4,%5,%6,%7}, {%8,%9}, {%0,%1,%2,%3};"
        : "+f"(d[0]), "+f"(d[1]), "+f"(d[2]), "+f"(d[3])
        : "r"(a[0]), "r"(a[1]), "r"(a[2]), "r"(a[3]), "r"(b[0]), "r"(b[1]));
}

// ---------------------------------------------------------------------------
// fp32 -> (hi, lo) bf16 splits
// ---------------------------------------------------------------------------
__device__ __forceinline__ void split1(float v, __nv_bfloat16& h, __nv_bfloat16& l) {
    h = __float2bfloat16(v);
    l = __float2bfloat16(v - __bfloat162float(h));
}

__global__ void split_bf16_kernel(const float* __restrict__ src,
                                  __nv_bfloat16* __restrict__ hi,
                                  __nv_bfloat16* __restrict__ lo, int n4) {
    int i = blockIdx.x * blockDim.x + threadIdx.x;
    if (i >= n4) return;
    float4 v = ((const float4*)src)[i];
    __nv_bfloat16 h0, h1, h2, h3, l0, l1, l2, l3;
    split1(v.x, h0, l0); split1(v.y, h1, l1);
    split1(v.z, h2, l2); split1(v.w, h3, l3);
    ((__nv_bfloat162*)hi)[2 * i + 0] = __nv_bfloat162(h0, h1);
    ((__nv_bfloat162*)hi)[2 * i + 1] = __nv_bfloat162(h2, h3);
    ((__nv_bfloat162*)lo)[2 * i + 0] = __nv_bfloat162(l0, l1);
    ((__nv_bfloat162*)lo)[2 * i + 1] = __nv_bfloat162(l2, l3);
}

// all 4 weights in one launch; 1024 blocks per weight
__global__ void split_w4_kernel(const float* __restrict__ s0, const float* __restrict__ s1,
                                const float* __restrict__ s2, const float* __restrict__ s3,
                                __nv_bfloat16* __restrict__ hi, __nv_bfloat16* __restrict__ lo) {
    int w = blockIdx.x >> 10;
    int i = (blockIdx.x & 1023) * 256 + threadIdx.x;     // < 262144
    const float* src = (w == 0) ? s0 : (w == 1) ? s1 : (w == 2) ? s2 : s3;
    float4 v = ((const float4*)src)[i];
    __nv_bfloat16 h0, h1, h2, h3, l0, l1, l2, l3;
    split1(v.x, h0, l0); split1(v.y, h1, l1);
    split1(v.z, h2, l2); split1(v.w, h3, l3);
    __nv_bfloat16* hp = hi + (size_t)w * WSZ;
    __nv_bfloat16* lp = lo + (size_t)w * WSZ;
    ((__nv_bfloat162*)hp)[2 * i + 0] = __nv_bfloat162(h0, h1);
    ((__nv_bfloat162*)hp)[2 * i + 1] = __nv_bfloat162(h2, h3);
    ((__nv_bfloat162*)lp)[2 * i + 0] = __nv_bfloat162(l0, l1);
    ((__nv_bfloat162*)lp)[2 * i + 1] = __nv_bfloat162(l2, l3);
}

// ---------------------------------------------------------------------------
// HMMA bf16-split GEMM, fused over several weight matrices.
// C_sel[M,1024] = A[M,1024] * B_sel[1024,1024]^T (+bias), sel = blockIdx.x/8
// CTA tile 128x128, BK=32, 8 warps (4x2), 3-stage cp.async, 2 CTAs/SM.
// ---------------------------------------------------------------------------
#define GM_BK 32
#define NSTAGE 3
#define STG_A_HI 0
#define STG_A_LO 8192
#define STG_B_HI 16384
#define STG_B_LO 24576
#define STG_BYTES 32768
#define GEMM_SMEM (NSTAGE * STG_BYTES)     // 98304
#define NCHUNK 32

__global__ __launch_bounds__(256, 2)
void gemm_tc(const __nv_bfloat16* __restrict__ Ahi, const __nv_bfloat16* __restrict__ Alo,
             const __nv_bfloat16* __restrict__ Bhi, const __nv_bfloat16* __restrict__ Blo,
             float* o0, float* o1, float* o2,
             const float* __restrict__ bias)
{
    extern __shared__ char smem[];
    const uint32_t sb = smem_u32(smem);
    const int tid  = threadIdx.x;
    const int wid  = tid >> 5;
    const int lane = tid & 31;
    const int warp_m = wid >> 1;
    const int warp_n = wid & 1;
    const int sel  = blockIdx.x >> 3;
    const int brow = blockIdx.y * 128;
    const int bcol = (blockIdx.x & 7) * 128;

    const __nv_bfloat16* Bh = Bhi + (size_t)sel * WSZ;
    const __nv_bfloat16* Bl = Blo + (size_t)sel * WSZ;
    float* C = (sel == 0) ? o0 : (sel == 1) ? o1 : o2;

    const int lr0 = tid >> 1;
    const int ls0 = (tid & 1) * 2;

    auto load_stage = [&](int c) {
        const uint32_t st = sb + (c % NSTAGE) * STG_BYTES;
        const int k0 = c * GM_BK;
        #pragma unroll
        for (int i = 0; i < 2; i++) {
            int s = ls0 + i;
            uint32_t so = swz64((uint32_t)(lr0 * 64 + s * 16));
            size_t ga = (size_t)(brow + lr0) * 1024 + k0 + s * 8;
            size_t gb = (size_t)(bcol + lr0) * 1024 + k0 + s * 8;
            cp16(st + STG_A_HI + so, Ahi + ga);
            cp16(st + STG_A_LO + so, Alo + ga);
            cp16(st + STG_B_HI + so, Bh + gb);
            cp16(st + STG_B_LO + so, Bl + gb);
        }
        CP_COMMIT();
    };

    float acc[2][8][4];
    #pragma unroll
    for (int i = 0; i < 2; i++)
        #pragma unroll
        for (int j = 0; j < 8; j++)
            #pragma unroll
            for (int q = 0; q < 4; q++) acc[i][j][q] = 0.f;

    load_stage(0);
    load_stage(1);

    const int a_row_l = (lane & 15);
    const int a_kb_l  = (lane >> 4) * 16;
    const int b_row_l = ((lane >> 4) * 8) + (lane & 7);
    const int b_kb_l  = ((lane >> 3) & 1) * 16;

    #pragma unroll 1
    for (int c = 0; c < NCHUNK; c++) {
        CP_WAIT1();
        __syncthreads();
        if (c + 2 < NCHUNK) load_stage(c + 2);
        else CP_COMMIT();

        const uint32_t st = sb + (c % NSTAGE) * STG_BYTES;

        #pragma unroll
        for (int ks = 0; ks < 2; ks++) {
            uint32_t ah[2][4], al[2][4];
            #pragma unroll
            for (int mf = 0; mf < 2; mf++) {
                int row = warp_m * 32 + mf * 16 + a_row_l;
                uint32_t off = swz64((uint32_t)(row * 64 + ks * 32 + a_kb_l));
                ldsm4(ah[mf], st + STG_A_HI + off);
                ldsm4(al[mf], st + STG_A_LO + off);
            }
            #pragma unroll
            for (int g = 0; g < 4; g++) {
                int row = warp_n * 64 + g * 16 + b_row_l;
                uint32_t off = swz64((uint32_t)(row * 64 + ks * 32 + b_kb_l));
                uint32_t bh[4], bl[4];
                ldsm4(bh, st + STG_B_HI + off);
                ldsm4(bl, st + STG_B_LO + off);
                #pragma unroll
                for (int mf = 0; mf < 2; mf++)
                    #pragma unroll
                    for (int h = 0; h < 2; h++) {
                        float* d = acc[mf][g * 2 + h];
                        mma16816(d, ah[mf], &bh[h * 2]);   // hi*hi
                        mma16816(d, ah[mf], &bl[h * 2]);   // hi*lo
                        mma16816(d, al[mf], &bh[h * 2]);   // lo*hi
                    }
            }
        }
    }

    // epilogue
    #pragma unroll
    for (int mf = 0; mf < 2; mf++) {
        int r0 = brow + warp_m * 32 + mf * 16 + (lane >> 2);
        #pragma unroll
        for (int nf = 0; nf < 8; nf++) {
            int col = bcol + warp_n * 64 + nf * 8 + (lane & 3) * 2;
            float b0 = 0.f, b1 = 0.f;
            if (bias) { b0 = bias[col]; b1 = bias[col + 1]; }
            float2 v0 = make_float2(acc[mf][nf][0] + b0, acc[mf][nf][1] + b1);
            float2 v1 = make_float2(acc[mf][nf][2] + b0, acc[mf][nf][3] + b1);
            *(float2*)&C[(size_t)r0 * 1024 + col]       = v0;
            *(float2*)&C[(size_t)(r0 + 8) * 1024 + col] = v1;
        }
    }
}

// ---------------------------------------------------------------------------
// Per-block attention, single pass. One CTA per (b, blk, head), 128 threads.
// Softmax via shift-invariant bound m_hat = scale*|q|*max_k|k|  (>= max score
// by Cauchy-Schwarz), so no max scan / no stored scores / no rescale.
// K and V staged in smem (67KB -> 3 CTAs/SM). Thread t owns query t (t<128);
// query 128 handled cooperatively at the end. Writes hi/lo bf16 split.
// ---------------------------------------------------------------------------
#define ATT_SMEM ((2 * BLKSZ * DKV + 64 + BLKSZ + 8 + 3) * (int)sizeof(float))

__global__ __launch_bounds__(128, 3)
void attn_block_kernel()
{
    const int h = blockIdx.x % NHEADS;
    const int j = (blockIdx.x / NHEADS) % NBLK;
    const int b = blockIdx.x / (NHEADS * NBLK);

    extern __shared__ float sm[];
    float* Ks   = sm;                        // 129*64
    float* Vs   = sm + BLKSZ * DKV;          // 129*64
    float* q128 = sm + 2 * BLKSZ * DKV;      // 64
    float* ps   = q128 + 64;                 // 129
    float* red  = ps + BLKSZ;                // 8 (warp maxes) + 1 (maxk2)

    const size_t base = ((size_t)b * NLEN + (size_t)j * BLKSZ) * DIMV + h * DKV;
    const int t = threadIdx.x;               // 0..127
    const float scale = 0.125f;              // 1/sqrt(64)

    // stage K and V (129 rows x 64 floats each); 2064 float4 per tensor
    for (int idx = t; idx < BLKSZ * (DKV / 4); idx += 128) {
        int r  = idx / (DKV / 4);
        int c4 = (idx % (DKV / 4)) * 4;
        *(float4*)&Ks[r * DKV + c4] = *(const float4*)&g_k[base + (size_t)r * DIMV + c4];
        *(float4*)&Vs[r * DKV + c4] = *(const float4*)&g_v[base + (size_t)r * DIMV + c4];
    }
    // thread 0..15 also stage q row 128 into smem for the cooperative tail
    if (t < 16)
        *(float4*)&q128[t * 4] = *(const float4*)&g_q[base + (size_t)128 * DIMV + t * 4];
    __syncthreads();

    // max_k |k|^2 (thread t -> row t; thread 0 also row 128)
    {
        float k2 = 0.f;
        #pragma unroll
        for (int d4 = 0; d4 < DKV / 4; d4++) {
            float4 kv = *(const float4*)&Ks[t * DKV + d4 * 4];
            k2 += kv.x * kv.x + kv.y * kv.y + kv.z * kv.z + kv.w * kv.w;
        }
        if (t == 0) {
            float e2 = 0.f;
            #pragma unroll
            for (int d4 = 0; d4 < DKV / 4; d4++) {
                float4 kv = *(const float4*)&Ks[128 * DKV + d4 * 4];
                e2 += kv.x * kv.x + kv.y * kv.y + kv.z * kv.z + kv.w * kv.w;
            }
            k2 = fmaxf(k2, e2);
        }
        #pragma unroll
        for (int o = 16; o > 0; o >>= 1)
            k2 = fmaxf(k2, __shfl_xor_sync(0xffffffffu, k2, o));
        if ((t & 31) == 0) red[t >> 5] = k2;
    }
    __syncthreads();
    const float maxk2 = fmaxf(fmaxf(red[0], red[1]), fmaxf(red[2], red[3]));

    // ---- main: query t ----
    float qr[DKV];
    float q2 = 0.f;
    #pragma unroll
    for (int d4 = 0; d4 < DKV / 4; d4++) {
        float4 qv = *(const float4*)&g_q[base + (size_t)t * DIMV + d4 * 4];
        qr[d4 * 4 + 0] = qv.x; qr[d4 * 4 + 1] = qv.y;
        qr[d4 * 4 + 2] = qv.z; qr[d4 * 4 + 3] = qv.w;
        q2 += qv.x * qv.x + qv.y * qv.y + qv.z * qv.z + qv.w * qv.w;
    }
    const float mhat = scale * sqrtf(q2 * maxk2);   // >= every score for this query

    float l = 0.f;
    float acc[DKV];
    #pragma unroll
    for (int d = 0; d < DKV; d++) acc[d] = 0.f;

    #pragma unroll 1
    for (int kk = 0; kk < BLKSZ; kk++) {
        const float* kr = &Ks[kk * DKV];
        float s0 = 0.f, s1 = 0.f, s2 = 0.f, s3 = 0.f;
        #pragma unroll
        for (int d4 = 0; d4 < DKV / 4; d4++) {
            float4 kv = *(const float4*)&kr[d4 * 4];
            s0 += qr[d4 * 4 + 0] * kv.x;
            s1 += qr[d4 * 4 + 1] * kv.y;
            s2 += qr[d4 * 4 + 2] * kv.z;
            s3 += qr[d4 * 4 + 3] * kv.w;
        }
        const float p = __expf(scale * ((s0 + s1) + (s2 + s3)) - mhat);
        l += p;
        const float* vr = &Vs[kk * DKV];
        #pragma unroll
        for (int d4 = 0; d4 < DKV / 4; d4++) {
            float4 vv = *(const float4*)&vr[d4 * 4];
            acc[d4 * 4 + 0] += p * vv.x;
            acc[d4 * 4 + 1] += p * vv.y;
            acc[d4 * 4 + 2] += p * vv.z;
            acc[d4 * 4 + 3] += p * vv.w;
        }
    }
    {
        const float inv = 1.f / l;
        const size_t ob = base + (size_t)t * DIMV;
        #pragma unroll
        for (int d2 = 0; d2 < DKV / 2; d2++) {
            float v0 = acc[2 * d2] * inv, v1 = acc[2 * d2 + 1] * inv;
            __nv_bfloat16 h0, h1, l0, l1;
            split1(v0, h0, l0); split1(v1, h1, l1);
            *(__nv_bfloat162*)&g_aoh[ob + 2 * d2] = __nv_bfloat162(h0, h1);
            *(__nv_bfloat162*)&g_aol[ob + 2 * d2] = __nv_bfloat162(l0, l1);
        }
    }

    // ---- cooperative tail: query 128 ----
    {
        float e2 = 0.f;
        #pragma unroll
        for (int d4 = 0; d4 < DKV / 4; d4++) {
            float4 qv = *(const float4*)&q128[d4 * 4];
            e2 += qv.x * qv.x + qv.y * qv.y + qv.z * qv.z + qv.w * qv.w;
        }
        const float mh8 = scale * sqrtf(e2 * maxk2);

        for (int kk = t; kk < BLKSZ; kk += 128) {
            const float* kr = &Ks[kk * DKV];
            float s0 = 0.f, s1 = 0.f, s2 = 0.f, s3 = 0.f;
            #pragma unroll
            for (int d4 = 0; d4 < DKV / 4; d4++) {
                float4 kv = *(const float4*)&kr[d4 * 4];
                float4 qv = *(const float4*)&q128[d4 * 4];
                s0 += qv.x * kv.x; s1 += qv.y * kv.y;
                s2 += qv.z * kv.z; s3 += qv.w * kv.w;
            }
            ps[kk] = __expf(scale * ((s0 + s1) + (s2 + s3)) - mh8);
        }
        __syncthreads();

        if (t < DKV) {
            float a = 0.f, lsum = 0.f;
            #pragma unroll 1
            for (int kk = 0; kk < BLKSZ; kk++) {
                float p = ps[kk];
                lsum += p;
                a += p * Vs[kk * DKV + t];
            }
            float v = a / lsum;
            __nv_bfloat16 hh, ll;
            split1(v, hh, ll);
            const size_t ob = base + (size_t)128 * DIMV + t;
            g_aoh[ob] = hh;
            g_aol[ob] = ll;
        }
    }
}

// ---------------------------------------------------------------------------
// Global attention over the 32 block-leader tokens (added into token 0).
// Reads/updates the hi/lo split representation.
// ---------------------------------------------------------------------------
__global__ void attn_global_kernel()
{
    const int h = blockIdx.x % NHEADS;
    const int b = blockIdx.x / NHEADS;
    const int t = threadIdx.x;           // query block index 0..31

    const size_t hb    = (size_t)h * DKV;
    const size_t qbase = ((size_t)b * NLEN + (size_t)t * BLKSZ) * DIMV + hb;

    float qr[DKV];
    #pragma unroll
    for (int d = 0; d < DKV; d++) qr[d] = g_q[qbase + d];

    const float scale = 0.125f;
    float sc[NBLK];
    float mx = -1e30f;
    for (int kk = 0; kk < NBLK; kk++) {
        const size_t kbase = ((size_t)b * NLEN + (size_t)kk * BLKSZ) * DIMV + hb;
        float s0 = 0.f, s1 = 0.f, s2 = 0.f, s3 = 0.f;
        #pragma unroll
        for (int d = 0; d < DKV; d += 4) {
            s0 += qr[d + 0] * g_k[kbase + d + 0];
            s1 += qr[d + 1] * g_k[kbase + d + 1];
            s2 += qr[d + 2] * g_k[kbase + d + 2];
            s3 += qr[d + 3] * g_k[kbase + d + 3];
        }
        float s = scale * ((s0 + s1) + (s2 + s3));
        sc[kk] = s;
        mx = fmaxf(mx, s);
    }
    float l = 0.f;
    for (int kk = 0; kk < NBLK; kk++) {
        float p = __expf(sc[kk] - mx);
        sc[kk] = p;
        l += p;
    }
    const float inv = 1.f / l;

    float acc[DKV];
    #pragma unroll
    for (int d = 0; d < DKV; d++) acc[d] = 0.f;
    for (int kk = 0; kk < NBLK; kk++) {
        const size_t vbase = ((size_t)b * NLEN + (size_t)kk * BLKSZ) * DIMV + hb;
        float p = sc[kk];
        #pragma unroll
        for (int d = 0; d < DKV; d++) acc[d] += p * g_v[vbase + d];
    }
    #pragma unroll
    for (int d = 0; d < DKV; d++) {
        float cur = __bfloat162float(g_aoh[qbase + d]) + __bfloat162float(g_aol[qbase + d]);
        float nv  = cur + acc[d] * inv;
        __nv_bfloat16 hh, ll;
        split1(nv, hh, ll);
        g_aoh[qbase + d] = hh;
        g_aol[qbase + d] = ll;
    }
}

// ---------------------------------------------------------------------------
// launcher
// ---------------------------------------------------------------------------
extern "C" void kernel_launch(void* const* d_in, const int* in_sizes, int n_in,
                              void* d_out, int out_size)
{
    const float* x  = (const float*)d_in[0];
    const float* Wq = (const float*)d_in[1];
    const float* Wk = (const float*)d_in[2];
    const float* Wv = (const float*)d_in[3];
    const float* Wo = (const float*)d_in[4];
    const float* bo = (const float*)d_in[5];
    float* out = (float*)d_out;

    float *qp, *kp, *vp;
    cudaGetSymbolAddress((void**)&qp,  g_q);
    cudaGetSymbolAddress((void**)&kp,  g_k);
    cudaGetSymbolAddress((void**)&vp,  g_v);
    __nv_bfloat16 *xh, *xl, *aoh, *aol, *wh, *wl;
    cudaGetSymbolAddress((void**)&xh,  g_xh);
    cudaGetSymbolAddress((void**)&xl,  g_xl);
    cudaGetSymbolAddress((void**)&aoh, g_aoh);
    cudaGetSymbolAddress((void**)&aol, g_aol);
    cudaGetSymbolAddress((void**)&wh,  g_wh);
    cudaGetSymbolAddress((void**)&wl,  g_wl);

    cudaFuncSetAttribute(gemm_tc,
                         cudaFuncAttributeMaxDynamicSharedMemorySize, GEMM_SMEM);
    cudaFuncSetAttribute(attn_block_kernel,
                         cudaFuncAttributeMaxDynamicSharedMemorySize, ATT_SMEM);

    // launch 0: all weight splits
    split_w4_kernel<<<4096, 256>>>(Wq, Wk, Wv, Wo, wh, wl);
    // launch 1: x split
    {
        int n4 = MROWS * DIMV / 4;
        split_bf16_kernel<<<(n4 + 255) / 256, 256>>>(x, xh, xl, n4);
    }
    // launch 2: fused QKV projection
    gemm_tc<<<dim3(24, MROWS / 128), 256, GEMM_SMEM>>>(
        xh, xl, wh, wl, qp, kp, vp, nullptr);
    // launch 3: per-block attention (single-pass, writes hi/lo split)
    attn_block_kernel<<<BATCH * NBLK * NHEADS, 128, ATT_SMEM>>>();
    // launch 4: global leader-token attention (updates split)
    attn_global_kernel<<<BATCH * NHEADS, 32>>>();
    // launch 5: output projection + bias
    gemm_tc<<<dim3(8, MROWS / 128), 256, GEMM_SMEM>>>(
        aoh, aol, wh + 3 * (size_t)WSZ, wl + 3 * (size_t)WSZ, out, out, out, bo);
}